// round 3
// baseline (speedup 1.0000x reference)
#include <cuda_runtime.h>
#include <cstdint>

// Problem constants
#define Bsz 32
#define Tlen 1024
#define Idim 512
#define Hdim 512

// Scratch for the input projection (device global: no allocation allowed)
__device__ float g_xproj[(size_t)Bsz * Tlen * Hdim];  // 64 MB

// ---------------------------------------------------------------------------
// packed f32x2 helpers (FFMA2 — ptxas never auto-fuses; PTX-only)
// ---------------------------------------------------------------------------
using u64 = unsigned long long;
__device__ __forceinline__ u64 pk2(float lo, float hi) {
    u64 r; asm("mov.b64 %0,{%1,%2};" : "=l"(r) : "f"(lo), "f"(hi)); return r;
}
__device__ __forceinline__ float2 upk2(u64 v) {
    float2 f; asm("mov.b64 {%0,%1},%2;" : "=f"(f.x), "=f"(f.y) : "l"(v)); return f;
}
__device__ __forceinline__ u64 fma2(u64 a, u64 b, u64 c) {
    u64 d; asm("fma.rn.f32x2 %0,%1,%2,%3;" : "=l"(d) : "l"(a), "l"(b), "l"(c)); return d;
}
__device__ __forceinline__ u64 add2(u64 a, u64 b) {
    u64 d; asm("add.rn.f32x2 %0,%1,%2;" : "=l"(d) : "l"(a), "l"(b)); return d;
}
__device__ __forceinline__ u64 mul2(u64 a, u64 b) {
    u64 d; asm("mul.rn.f32x2 %0,%1,%2;" : "=l"(d) : "l"(a), "l"(b)); return d;
}

__device__ __forceinline__ uint32_t s2u(const void* p) {
    uint32_t a;
    asm("{ .reg .u64 t; cvta.to.shared.u64 t, %1; cvt.u32.u64 %0, t; }"
        : "=r"(a) : "l"(p));
    return a;
}
__device__ __forceinline__ void st_remote_f32(uint32_t laddr, uint32_t rank, float v) {
    asm volatile(
        "{ .reg .b32 r; mapa.shared::cluster.u32 r, %0, %1; st.shared::cluster.f32 [r], %2; }"
        :: "r"(laddr), "r"(rank), "f"(v) : "memory");
}
__device__ __forceinline__ void mbar_arrive_remote(uint32_t mb, uint32_t rank) {
    asm volatile(
        "{ .reg .b32 r; mapa.shared::cluster.u32 r, %0, %1;\n\t"
        "mbarrier.arrive.release.cluster.shared::cluster.b64 _, [r]; }"
        :: "r"(mb), "r"(rank) : "memory");
}
__device__ __forceinline__ void mbar_wait_parity_cluster(uint32_t mb, uint32_t parity) {
    asm volatile(
        "{\n\t"
        ".reg .pred P;\n\t"
        "WLOOP_%=:\n\t"
        "mbarrier.try_wait.parity.acquire.cluster.shared::cta.b64 P, [%0], %1, 0x989680;\n\t"
        "@P bra.uni WDONE_%=;\n\t"
        "bra.uni WLOOP_%=;\n\t"
        "WDONE_%=:\n\t"
        "}"
        :: "r"(mb), "r"(parity) : "memory");
}
__device__ __forceinline__ void cluster_sync_asm() {
    asm volatile("barrier.cluster.arrive.aligned;" ::: "memory");
    asm volatile("barrier.cluster.wait.aligned;" ::: "memory");
}

// ---------------------------------------------------------------------------
// Kernel 1: xproj[m, h] = sum_i X[m, i] * Wih[h, i] + bih[h] + bhh[h]
//   fp32 SGEMM 128x128x16, 8x8 micro-tile, inner loop in fma.rn.f32x2
// ---------------------------------------------------------------------------
__global__ void __launch_bounds__(256) xproj_kernel(
    const float* __restrict__ X,     // [32768, 512]
    const float* __restrict__ Wih,   // [512, 512]
    const float* __restrict__ bih,
    const float* __restrict__ bhh)
{
    const int BM = 128, BN = 128, BK = 16;
    __shared__ __align__(16) float As[BK][BM + 4];
    __shared__ __align__(16) float Bs[BK][BN + 4];

    const int tid = threadIdx.x;
    const int m0 = blockIdx.y * BM;
    const int n0 = blockIdx.x * BN;
    const int tx = tid & 15;        // n micro-tile
    const int ty = tid >> 4;        // m micro-tile

    u64 acc2[8][4];
#pragma unroll
    for (int i = 0; i < 8; ++i)
#pragma unroll
        for (int j = 0; j < 4; ++j) acc2[i][j] = 0ull;

    for (int k0 = 0; k0 < Idim; k0 += BK) {
#pragma unroll
        for (int q = 0; q < 2; ++q) {
            int lin = tid + 256 * q;          // 0..511
            int m = lin >> 2;                 // 0..127
            int kv = (lin & 3) << 2;          // 0,4,8,12
            float4 va = *(const float4*)(X + (size_t)(m0 + m) * Idim + k0 + kv);
            As[kv + 0][m] = va.x; As[kv + 1][m] = va.y;
            As[kv + 2][m] = va.z; As[kv + 3][m] = va.w;
            float4 vb = *(const float4*)(Wih + (size_t)(n0 + m) * Idim + k0 + kv);
            Bs[kv + 0][m] = vb.x; Bs[kv + 1][m] = vb.y;
            Bs[kv + 2][m] = vb.z; Bs[kv + 3][m] = vb.w;
        }
        __syncthreads();

#pragma unroll
        for (int kk = 0; kk < BK; ++kk) {
            float ra[8];
            *(float4*)&ra[0] = *(const float4*)&As[kk][ty * 8];
            *(float4*)&ra[4] = *(const float4*)&As[kk][ty * 8 + 4];
            ulonglong2 rbA = *(const ulonglong2*)&Bs[kk][tx * 8];
            ulonglong2 rbB = *(const ulonglong2*)&Bs[kk][tx * 8 + 4];
            u64 rb2[4] = { rbA.x, rbA.y, rbB.x, rbB.y };
#pragma unroll
            for (int i = 0; i < 8; ++i) {
                u64 rap = pk2(ra[i], ra[i]);
#pragma unroll
                for (int j = 0; j < 4; ++j)
                    acc2[i][j] = fma2(rap, rb2[j], acc2[i][j]);
            }
        }
        __syncthreads();
    }

    u64 bs2[4];
#pragma unroll
    for (int j = 0; j < 4; ++j) {
        float blo = bih[n0 + tx * 8 + 2 * j] + bhh[n0 + tx * 8 + 2 * j];
        float bhi = bih[n0 + tx * 8 + 2 * j + 1] + bhh[n0 + tx * 8 + 2 * j + 1];
        bs2[j] = pk2(blo, bhi);
    }

#pragma unroll
    for (int i = 0; i < 8; ++i) {
        float2 p0 = upk2(add2(acc2[i][0], bs2[0]));
        float2 p1 = upk2(add2(acc2[i][1], bs2[1]));
        float2 p2 = upk2(add2(acc2[i][2], bs2[2]));
        float2 p3 = upk2(add2(acc2[i][3], bs2[3]));
        float* crow = g_xproj + (size_t)(m0 + ty * 8 + i) * Hdim + n0 + tx * 8;
        *(float4*)(crow)     = make_float4(p0.x, p0.y, p1.x, p1.y);
        *(float4*)(crow + 4) = make_float4(p2.x, p2.y, p3.x, p3.y);
    }
}

// ---------------------------------------------------------------------------
// Kernel 2: the recurrence.
//   Grid (8 H-slices) x (16 batch-groups); cluster = 8 CTAs (one batch-group).
//   Key restructure: Whh·(Σk kern_k h_{t-1-k}) = Σk kern_k (Whh·h_{t-1-k}).
//   Each step does ONE GEMM on the freshly exchanged h_{t-1} (straight from
//   the smem ring, no interpolation pass, no extra barrier) and applies the
//   4-tap Lagrange kernel to a register ring of M = Whh·h partials.
//   GEMM inner loop is fma.rn.f32x2 (2 K-lanes packed, batch-major history).
//   Cross-CTA exchange: remote DSMEM stores + mbarrier release/acquire at
//   cluster scope (no cluster.sync -> no per-step L1D flush).
//   xproj staged into smem 8 steps at a time, prefetched a group ahead.
// ---------------------------------------------------------------------------
__global__ void __launch_bounds__(256, 1) __cluster_dims__(8, 1, 1)
rnn_kernel(const float* __restrict__ Whh,   // [512, 512]
           const float* __restrict__ kern,  // [4]
           float* __restrict__ out_states,  // [B, T, H]
           float* __restrict__ out_last)    // [B, H]
{
    __shared__ __align__(16) float hist[4][2][Hdim];   // 16 KB h ring, batch-major
    __shared__ __align__(16) float xs[2][8][64];       // 4 KB xproj stage
    __shared__ __align__(8)  unsigned long long mbar;

    const int tid   = threadIdx.x;
    const int slice = blockIdx.x;          // 0..7 == cluster rank
    const int grp   = blockIdx.y;          // 0..15
    const int b0    = grp * 2;
    const int b1    = b0 + 1;
    const int jl    = tid >> 2;            // 0..63 output within slice
    const int split = tid & 3;             // interleaved K-split 0..3
    const int jg    = slice * 64 + jl;     // global output index

    // Pin this thread's Whh slice in registers as packed pairs.
    // Chunk m covers K indices split*4 + 16m .. +3 (stride 64B -> 4 ulonglong2).
    u64 w2[64];
    {
        const ulonglong2* wru =
            (const ulonglong2*)(Whh + (size_t)jg * Hdim + split * 4);
#pragma unroll
        for (int m = 0; m < 32; ++m) {
            ulonglong2 u = wru[4 * m];
            w2[2 * m]     = u.x;
            w2[2 * m + 1] = u.y;
        }
    }
    const float k0s = kern[0], k1s = kern[1], k2s = kern[2], k3s = kern[3];
    const u64 kk0 = pk2(k0s, k0s), kk1 = pk2(k1s, k1s);
    const u64 kk2 = pk2(k2s, k2s), kk3 = pk2(k3s, k3s);

    // Zero history ring; init mbarrier (8 arrivals per phase)
    for (int i = tid; i < 4 * 2 * Hdim; i += 256)
        ((float*)hist)[i] = 0.f;
    const uint32_t mb = s2u(&mbar);
    if (tid == 0)
        asm volatile("mbarrier.init.shared.b64 [%0], 8;" :: "r"(mb) : "memory");
    cluster_sync_asm();   // ring zero + mbar init visible cluster-wide

    // xproj staging: one float4 per thread per 8-step group
    const int pb   = tid >> 7;          // batch within pair
    const int ptr_ = (tid >> 4) & 7;    // t-row within group
    const int ph4  = (tid & 15) * 4;    // h offset within slice
    const float* xsrc = g_xproj + (size_t)(b0 + pb) * Tlen * Hdim
                        + (size_t)ptr_ * Hdim + slice * 64 + ph4;
    float4 xpre = *(const float4*)(xsrc);   // group 0

    float* os0 = out_states + (size_t)b0 * Tlen * Hdim + jg;
    float* os1 = out_states + (size_t)b1 * Tlen * Hdim + jg;

    // Register ring of M = Whh.h (reduced, replicated across the 4 split lanes)
    u64 ring0 = 0ull, ring1 = 0ull, ring2 = 0ull;

    for (int t = 0; t < Tlen; ++t) {
        // Wait for every CTA's h_{t-1} slice to have landed in our ring
        if (t > 0)
            mbar_wait_parity_cluster(mb, (t - 1) & 1);

        // Stage the next 8 steps of xproj
        if ((t & 7) == 0) {
            *(float4*)&xs[pb][ptr_][ph4] = xpre;
            __syncthreads();
            if (t + 8 < Tlen)
                xpre = *(const float4*)(xsrc + (size_t)(t + 8) * Hdim);
        }

        // GEMM partial: Mp_b = sum_{i in my chunks} w[i] * h_{t-1}[b][i]
        const float* hb0 = &hist[(t - 1) & 3][0][split * 4];
        const float* hb1 = &hist[(t - 1) & 3][1][split * 4];
        u64 a0 = 0ull, c0 = 0ull, a1 = 0ull, c1 = 0ull;
#pragma unroll
        for (int m = 0; m < 32; ++m) {
            ulonglong2 h0 = *(const ulonglong2*)(hb0 + 16 * m);
            ulonglong2 h1 = *(const ulonglong2*)(hb1 + 16 * m);
            a0 = fma2(w2[2 * m],     h0.x, a0);
            c0 = fma2(w2[2 * m + 1], h0.y, c0);
            a1 = fma2(w2[2 * m],     h1.x, a1);
            c1 = fma2(w2[2 * m + 1], h1.y, c1);
        }
        float2 s0 = upk2(add2(a0, c0));
        float2 s1 = upk2(add2(a1, c1));
        float Mp0 = s0.x + s0.y;
        float Mp1 = s1.x + s1.y;

        // Butterfly-reduce across the 4 K-split lanes (all lanes get full M)
        Mp0 += __shfl_xor_sync(0xFFFFFFFFu, Mp0, 1);
        Mp0 += __shfl_xor_sync(0xFFFFFFFFu, Mp0, 2);
        Mp1 += __shfl_xor_sync(0xFFFFFFFFu, Mp1, 1);
        Mp1 += __shfl_xor_sync(0xFFFFFFFFu, Mp1, 2);
        const u64 M = pk2(Mp0, Mp1);

        // 4-tap Lagrange on the M ring: r = k0*M_{t-1} + ... + k3*M_{t-4}
        u64 r = fma2(kk0, M, fma2(kk1, ring0, fma2(kk2, ring1, mul2(kk3, ring2))));
        ring2 = ring1; ring1 = ring0; ring0 = M;

        float2 rf = upk2(r);
        float xv0 = xs[0][t & 7][jl];
        float xv1 = xs[1][t & 7][jl];
        float h0v = tanhf(rf.x + xv0);   // xv already includes bih + bhh
        float h1v = tanhf(rf.y + xv1);

        // Output stores (distributed across split lanes)
        if (split == 0) os0[(size_t)t * Hdim] = h0v;
        else if (split == 1) os1[(size_t)t * Hdim] = h1v;
        if (t == Tlen - 1) {
            if (split == 2) out_last[(size_t)b0 * Hdim + jg] = h0v;
            if (split == 3) out_last[(size_t)b1 * Hdim + jg] = h1v;
        }

        // Exchange: each split lane stores h to 2 cluster ranks (8 total)
        if (t < Tlen - 1) {
            const int slot = t & 3;
            uint32_t l0 = s2u(&hist[slot][0][jg]);
            uint32_t l1 = s2u(&hist[slot][1][jg]);
            st_remote_f32(l0, 2 * split, h0v);
            st_remote_f32(l1, 2 * split, h1v);
            st_remote_f32(l0, 2 * split + 1, h0v);
            st_remote_f32(l1, 2 * split + 1, h1v);
        }
        __syncthreads();    // all remote stores issued before arrivals
        if (t < Tlen - 1 && tid < 8)
            mbar_arrive_remote(mb, (uint32_t)tid);
    }

    // No CTA may exit while a peer's remote stores could still target it
    cluster_sync_asm();
}

// ---------------------------------------------------------------------------
extern "C" void kernel_launch(void* const* d_in, const int* in_sizes, int n_in,
                              void* d_out, int out_size)
{
    (void)in_sizes; (void)n_in; (void)out_size;
    const float* x    = (const float*)d_in[0];   // [32, 1024, 512]
    const float* Wih  = (const float*)d_in[1];   // [512, 512]
    const float* Whh  = (const float*)d_in[2];   // [512, 512]
    const float* bih  = (const float*)d_in[3];   // [512]
    const float* bhh  = (const float*)d_in[4];   // [512]
    const float* kern = (const float*)d_in[5];   // [4]

    float* out        = (float*)d_out;
    float* out_states = out;                                   // [32,1024,512]
    float* out_last   = out + (size_t)Bsz * Tlen * Hdim;       // [32,512]

    // 1) Input projection GEMM (+bih+bhh folded in)
    dim3 gg(Hdim / 128, (Bsz * Tlen) / 128);   // (4, 256)
    xproj_kernel<<<gg, 256>>>(x, Wih, bih, bhh);

    // 2) Sequential recurrence: 16 clusters of 8 CTAs
    dim3 gr(8, 16);
    rnn_kernel<<<gr, 256>>>(Whh, kern, out_states, out_last);
}

// round 4
// speedup vs baseline: 1.1523x; 1.1523x over previous
#include <cuda_runtime.h>
#include <cstdint>

// Problem constants
#define Bsz 32
#define Tlen 1024
#define Idim 512
#define Hdim 512

// Scratch for the input projection (device global: no allocation allowed)
__device__ float g_xproj[(size_t)Bsz * Tlen * Hdim];  // 64 MB

// ---------------------------------------------------------------------------
// packed f32x2 helpers (FFMA2 — ptxas never auto-fuses; PTX-only)
// ---------------------------------------------------------------------------
using u64 = unsigned long long;
__device__ __forceinline__ u64 pk2(float lo, float hi) {
    u64 r; asm("mov.b64 %0,{%1,%2};" : "=l"(r) : "f"(lo), "f"(hi)); return r;
}
__device__ __forceinline__ float2 upk2(u64 v) {
    float2 f; asm("mov.b64 {%0,%1},%2;" : "=f"(f.x), "=f"(f.y) : "l"(v)); return f;
}
__device__ __forceinline__ u64 fma2(u64 a, u64 b, u64 c) {
    u64 d; asm("fma.rn.f32x2 %0,%1,%2,%3;" : "=l"(d) : "l"(a), "l"(b), "l"(c)); return d;
}
__device__ __forceinline__ u64 add2(u64 a, u64 b) {
    u64 d; asm("add.rn.f32x2 %0,%1,%2;" : "=l"(d) : "l"(a), "l"(b)); return d;
}
__device__ __forceinline__ u64 mul2(u64 a, u64 b) {
    u64 d; asm("mul.rn.f32x2 %0,%1,%2;" : "=l"(d) : "l"(a), "l"(b)); return d;
}

__device__ __forceinline__ uint32_t s2u(const void* p) {
    uint32_t a;
    asm("{ .reg .u64 t; cvta.to.shared.u64 t, %1; cvt.u32.u64 %0, t; }"
        : "=r"(a) : "l"(p));
    return a;
}
__device__ __forceinline__ uint32_t mapa_rank(uint32_t laddr, uint32_t rank) {
    uint32_t r;
    asm("mapa.shared::cluster.u32 %0, %1, %2;" : "=r"(r) : "r"(laddr), "r"(rank));
    return r;
}
__device__ __forceinline__ void st_cluster_f32(uint32_t addr, float v) {
    asm volatile("st.shared::cluster.f32 [%0], %1;" :: "r"(addr), "f"(v) : "memory");
}
__device__ __forceinline__ void mbar_arrive_addr(uint32_t addr) {
    asm volatile("mbarrier.arrive.release.cluster.shared::cluster.b64 _, [%0];"
                 :: "r"(addr) : "memory");
}
__device__ __forceinline__ void mbar_wait_parity_cluster(uint32_t mb, uint32_t parity) {
    asm volatile(
        "{\n\t"
        ".reg .pred P;\n\t"
        "WLOOP_%=:\n\t"
        "mbarrier.try_wait.parity.acquire.cluster.shared::cta.b64 P, [%0], %1, 0x989680;\n\t"
        "@P bra.uni WDONE_%=;\n\t"
        "bra.uni WLOOP_%=;\n\t"
        "WDONE_%=:\n\t"
        "}"
        :: "r"(mb), "r"(parity) : "memory");
}
__device__ __forceinline__ void cluster_sync_asm() {
    asm volatile("barrier.cluster.arrive.aligned;" ::: "memory");
    asm volatile("barrier.cluster.wait.aligned;" ::: "memory");
}
__device__ __forceinline__ u64 shflx2(u64 v, int m) {
    float2 f = upk2(v);
    f.x = __shfl_xor_sync(0xFFFFFFFFu, f.x, m);
    f.y = __shfl_xor_sync(0xFFFFFFFFu, f.y, m);
    return pk2(f.x, f.y);
}

// ---------------------------------------------------------------------------
// Kernel 1: xproj[m, h] = sum_i X[m, i] * Wih[h, i] + bih[h] + bhh[h]
//   fp32 SGEMM 128x128x16, 8x8 micro-tile, inner loop in fma.rn.f32x2
// ---------------------------------------------------------------------------
__global__ void __launch_bounds__(256) xproj_kernel(
    const float* __restrict__ X,     // [32768, 512]
    const float* __restrict__ Wih,   // [512, 512]
    const float* __restrict__ bih,
    const float* __restrict__ bhh)
{
    const int BM = 128, BN = 128, BK = 16;
    __shared__ __align__(16) float As[BK][BM + 4];
    __shared__ __align__(16) float Bs[BK][BN + 4];

    const int tid = threadIdx.x;
    const int m0 = blockIdx.y * BM;
    const int n0 = blockIdx.x * BN;
    const int tx = tid & 15;
    const int ty = tid >> 4;

    u64 acc2[8][4];
#pragma unroll
    for (int i = 0; i < 8; ++i)
#pragma unroll
        for (int j = 0; j < 4; ++j) acc2[i][j] = 0ull;

    for (int k0 = 0; k0 < Idim; k0 += BK) {
#pragma unroll
        for (int q = 0; q < 2; ++q) {
            int lin = tid + 256 * q;
            int m = lin >> 2;
            int kv = (lin & 3) << 2;
            float4 va = *(const float4*)(X + (size_t)(m0 + m) * Idim + k0 + kv);
            As[kv + 0][m] = va.x; As[kv + 1][m] = va.y;
            As[kv + 2][m] = va.z; As[kv + 3][m] = va.w;
            float4 vb = *(const float4*)(Wih + (size_t)(n0 + m) * Idim + k0 + kv);
            Bs[kv + 0][m] = vb.x; Bs[kv + 1][m] = vb.y;
            Bs[kv + 2][m] = vb.z; Bs[kv + 3][m] = vb.w;
        }
        __syncthreads();

#pragma unroll
        for (int kk = 0; kk < BK; ++kk) {
            float ra[8];
            *(float4*)&ra[0] = *(const float4*)&As[kk][ty * 8];
            *(float4*)&ra[4] = *(const float4*)&As[kk][ty * 8 + 4];
            ulonglong2 rbA = *(const ulonglong2*)&Bs[kk][tx * 8];
            ulonglong2 rbB = *(const ulonglong2*)&Bs[kk][tx * 8 + 4];
            u64 rb2[4] = { rbA.x, rbA.y, rbB.x, rbB.y };
#pragma unroll
            for (int i = 0; i < 8; ++i) {
                u64 rap = pk2(ra[i], ra[i]);
#pragma unroll
                for (int j = 0; j < 4; ++j)
                    acc2[i][j] = fma2(rap, rb2[j], acc2[i][j]);
            }
        }
        __syncthreads();
    }

    u64 bs2[4];
#pragma unroll
    for (int j = 0; j < 4; ++j) {
        float blo = bih[n0 + tx * 8 + 2 * j] + bhh[n0 + tx * 8 + 2 * j];
        float bhi = bih[n0 + tx * 8 + 2 * j + 1] + bhh[n0 + tx * 8 + 2 * j + 1];
        bs2[j] = pk2(blo, bhi);
    }

#pragma unroll
    for (int i = 0; i < 8; ++i) {
        float2 p0 = upk2(add2(acc2[i][0], bs2[0]));
        float2 p1 = upk2(add2(acc2[i][1], bs2[1]));
        float2 p2 = upk2(add2(acc2[i][2], bs2[2]));
        float2 p3 = upk2(add2(acc2[i][3], bs2[3]));
        float* crow = g_xproj + (size_t)(m0 + ty * 8 + i) * Hdim + n0 + tx * 8;
        *(float4*)(crow)     = make_float4(p0.x, p0.y, p1.x, p1.y);
        *(float4*)(crow + 4) = make_float4(p2.x, p2.y, p3.x, p3.y);
    }
}

// ---------------------------------------------------------------------------
// Kernel 2: the recurrence.
//   Grid (8 H-slices) x (16 batch-groups); cluster = 8 CTAs.
//   CTA: 256 threads = 32 jlp-groups x 8 splits; thread owns 2 output rows
//   (jg0 = slice*64 + jlp*2, jg1 = jg0+1), both batches, 64 K-values.
//   M-ring restructure: r_t = k0*M_{t-1}+..+k3*M_{t-4}, M = Whh*h.
//   Per step: wait(mbar) -> GEMV (reg Whh, fma.rn.f32x2) -> 8-lane butterfly
//   -> 1 tanh/lane -> 4 remote st.32 (precomputed mapa bases, rank group by
//   lane) -> syncwarp -> per-warp arrive to all 8 ranks (release) ->
//   output STG LAST (off the barrier's release path — key change).
// ---------------------------------------------------------------------------
__global__ void __launch_bounds__(256, 1) __cluster_dims__(8, 1, 1)
rnn_kernel(const float* __restrict__ Whh,   // [512, 512]
           const float* __restrict__ kern,  // [4]
           float* __restrict__ out_states,  // [B, T, H]
           float* __restrict__ out_last)    // [B, H]
{
    __shared__ __align__(16) float hist[4][2][Hdim];   // 16 KB h ring, batch-major
    __shared__ __align__(16) float xs[2][8][64];       // 4 KB xproj stage
    __shared__ __align__(8)  unsigned long long mbar;

    const int tid   = threadIdx.x;
    const int slice = blockIdx.x;          // 0..7 == cluster rank
    const int grp   = blockIdx.y;          // 0..15
    const int b0    = grp * 2;
    const int jlp   = tid >> 3;            // 0..31  (pair of output rows)
    const int split = tid & 7;             // K-split / role lane 0..7
    const int jg0   = slice * 64 + jlp * 2;
    const int jg1   = jg0 + 1;

    // Whh rows jg0/jg1, K chunks c = split + 8m (4 floats each), packed pairs.
    u64 wA[32], wB[32];
#pragma unroll
    for (int m = 0; m < 16; ++m) {
        ulonglong2 ua = *(const ulonglong2*)(Whh + (size_t)jg0 * Hdim + 4 * (split + 8 * m));
        ulonglong2 ub = *(const ulonglong2*)(Whh + (size_t)jg1 * Hdim + 4 * (split + 8 * m));
        wA[2 * m] = ua.x; wA[2 * m + 1] = ua.y;
        wB[2 * m] = ub.x; wB[2 * m + 1] = ub.y;
    }
    const float k0s = kern[0], k1s = kern[1], k2s = kern[2], k3s = kern[3];

    // Zero history ring; init mbarrier (64 arrivals = 8 CTAs x 8 warps)
    for (int i = tid; i < 4 * 2 * Hdim; i += 256)
        ((float*)hist)[i] = 0.f;
    const uint32_t mb = s2u(&mbar);
    if (tid == 0)
        asm volatile("mbarrier.init.shared.b64 [%0], 64;" :: "r"(mb) : "memory");
    cluster_sync_asm();   // ring zero + mbar init visible cluster-wide

    // This thread's activated value: v = split&3 -> (row rsel, batch bsel).
    const int v    = split & 3;
    const int bsel = v & 1;
    const int rsel = v >> 1;
    const int jgv  = jg0 + rsel;           // output index of my value
    // Precompute 4 remote hist addresses (rank group 0-3 or 4-7) + fixed offset
    const uint32_t hb = s2u(hist);
    const int      qb = (split < 4) ? 0 : 4;
    const uint32_t hoff = (uint32_t)(bsel * (Hdim * 4) + jgv * 4);
    uint32_t rdst[4];
#pragma unroll
    for (int q = 0; q < 4; ++q)
        rdst[q] = mapa_rank(hb, qb + q) + hoff;
    // Per-warp arrive targets: lanes 0..7 arrive to rank = lane
    const int lane = tid & 31;
    uint32_t mb_r = 0;
    if (lane < 8) mb_r = mapa_rank(mb, lane);

    // xproj staging: one float4 per thread per 8-step group
    const int pb   = tid >> 7;
    const int ptr_ = (tid >> 4) & 7;
    const int ph4  = (tid & 15) * 4;
    const float* xsrc = g_xproj + (size_t)(b0 + pb) * Tlen * Hdim
                        + (size_t)ptr_ * Hdim + slice * 64 + ph4;
    float4 xpre = *(const float4*)(xsrc);   // group 0

    // Output pointer for my value (split<4 store states; split>=4 store last)
    float* osv = out_states + (size_t)(b0 + bsel) * Tlen * Hdim + jgv;

    // Register M-ring (packed per output row: (b0, b1))
    u64 rA0 = 0ull, rA1 = 0ull, rA2 = 0ull;   // M_{t-1..t-3} for row jg0
    u64 rB0 = 0ull, rB1 = 0ull, rB2 = 0ull;   // ... row jg1
    const u64 kk0 = pk2(k0s, k0s), kk1 = pk2(k1s, k1s);
    const u64 kk2 = pk2(k2s, k2s), kk3 = pk2(k3s, k3s);

    for (int t = 0; t < Tlen; ++t) {
        if (t > 0)
            mbar_wait_parity_cluster(mb, (t - 1) & 1);

        // Stage the next 8 steps of xproj
        if ((t & 7) == 0) {
            *(float4*)&xs[pb][ptr_][ph4] = xpre;
            __syncthreads();
            if (t + 8 < Tlen)
                xpre = *(const float4*)(xsrc + (size_t)(t + 8) * Hdim);
        }

        // GEMV partials on h_{t-1}: 8 independent fma2 chains
        const float* h0p = &hist[(t - 1) & 3][0][4 * split];
        const float* h1p = &hist[(t - 1) & 3][1][4 * split];
        u64 aA0 = 0ull, aA0b = 0ull, aA1 = 0ull, aA1b = 0ull;
        u64 aB0 = 0ull, aB0b = 0ull, aB1 = 0ull, aB1b = 0ull;
#pragma unroll
        for (int m = 0; m < 16; ++m) {
            ulonglong2 h0 = *(const ulonglong2*)(h0p + 32 * m);
            ulonglong2 h1 = *(const ulonglong2*)(h1p + 32 * m);
            aA0  = fma2(wA[2 * m],     h0.x, aA0);
            aA0b = fma2(wA[2 * m + 1], h0.y, aA0b);
            aA1  = fma2(wA[2 * m],     h1.x, aA1);
            aA1b = fma2(wA[2 * m + 1], h1.y, aA1b);
            aB0  = fma2(wB[2 * m],     h0.x, aB0);
            aB0b = fma2(wB[2 * m + 1], h0.y, aB0b);
            aB1  = fma2(wB[2 * m],     h1.x, aB1);
            aB1b = fma2(wB[2 * m + 1], h1.y, aB1b);
        }
        // Horizontal: P0 = (MA_b0, MA_b1), P1 = (MB_b0, MB_b1) partials
        float2 hA0 = upk2(add2(aA0, aA0b));
        float2 hA1 = upk2(add2(aA1, aA1b));
        float2 hB0 = upk2(add2(aB0, aB0b));
        float2 hB1 = upk2(add2(aB1, aB1b));
        u64 P0 = pk2(hA0.x + hA0.y, hA1.x + hA1.y);
        u64 P1 = pk2(hB0.x + hB0.y, hB1.x + hB1.y);

        // Butterfly over the 8 split lanes (lanes of one jlp are contiguous)
        P0 = add2(P0, shflx2(P0, 1)); P1 = add2(P1, shflx2(P1, 1));
        P0 = add2(P0, shflx2(P0, 2)); P1 = add2(P1, shflx2(P1, 2));
        P0 = add2(P0, shflx2(P0, 4)); P1 = add2(P1, shflx2(P1, 4));
        // P0/P1 now hold full M_t... for rows A/B (packed over batches)

        // 4-tap Lagrange on the register M-ring
        u64 rrA = fma2(kk0, P0, fma2(kk1, rA0, fma2(kk2, rA1, mul2(kk3, rA2))));
        u64 rrB = fma2(kk0, P1, fma2(kk1, rB0, fma2(kk2, rB1, mul2(kk3, rB2))));
        rA2 = rA1; rA1 = rA0; rA0 = P0;
        rB2 = rB1; rB1 = rB0; rB0 = P1;

        // Select this lane's value and activate (1 tanh per lane)
        float2 fA = upk2(rrA), fB = upk2(rrB);
        float pre = (v == 0) ? fA.x : (v == 1) ? fA.y : (v == 2) ? fB.x : fB.y;
        float hval = tanhf(pre + xs[bsel][t & 7][jlp * 2 + rsel]);

        // Exchange: my value to 4 ranks (other 4 covered by lane split^4)
        if (t < Tlen - 1) {
            const uint32_t soff = (uint32_t)((t & 3) * (2 * Hdim * 4));
            st_cluster_f32(rdst[0] + soff, hval);
            st_cluster_f32(rdst[1] + soff, hval);
            st_cluster_f32(rdst[2] + soff, hval);
            st_cluster_f32(rdst[3] + soff, hval);
            __syncwarp();
            if (lane < 8)
                mbar_arrive_addr(mb_r);     // release AFTER stores, BEFORE STG
        }

        // Output stores LAST — off the release path, drain in background
        if (split < 4)
            osv[(size_t)t * Hdim] = hval;
        else if (t == Tlen - 1)
            out_last[(size_t)(b0 + bsel) * Hdim + jgv] = hval;
    }

    // No CTA may exit while a peer's remote stores could still target it
    cluster_sync_asm();
}

// ---------------------------------------------------------------------------
extern "C" void kernel_launch(void* const* d_in, const int* in_sizes, int n_in,
                              void* d_out, int out_size)
{
    (void)in_sizes; (void)n_in; (void)out_size;
    const float* x    = (const float*)d_in[0];   // [32, 1024, 512]
    const float* Wih  = (const float*)d_in[1];   // [512, 512]
    const float* Whh  = (const float*)d_in[2];   // [512, 512]
    const float* bih  = (const float*)d_in[3];   // [512]
    const float* bhh  = (const float*)d_in[4];   // [512]
    const float* kern = (const float*)d_in[5];   // [4]

    float* out        = (float*)d_out;
    float* out_states = out;                                   // [32,1024,512]
    float* out_last   = out + (size_t)Bsz * Tlen * Hdim;       // [32,512]

    dim3 gg(Hdim / 128, (Bsz * Tlen) / 128);   // (4, 256)
    xproj_kernel<<<gg, 256>>>(x, Wih, bih, bhh);

    dim3 gr(8, 16);
    rnn_kernel<<<gr, 256>>>(Whh, kern, out_states, out_last);
}

// round 5
// speedup vs baseline: 1.5696x; 1.3622x over previous
#include <cuda_runtime.h>
#include <cstdint>

// Problem constants
#define Bsz 32
#define Tlen 1024
#define Idim 512
#define Hdim 512

// Scratch for the input projection (device global: no allocation allowed)
__device__ float g_xproj[(size_t)Bsz * Tlen * Hdim];  // 64 MB

// ---------------------------------------------------------------------------
// packed f32x2 helpers (FFMA2 — ptxas never auto-fuses; PTX-only)
// ---------------------------------------------------------------------------
using u64 = unsigned long long;
__device__ __forceinline__ u64 pk2(float lo, float hi) {
    u64 r; asm("mov.b64 %0,{%1,%2};" : "=l"(r) : "f"(lo), "f"(hi)); return r;
}
__device__ __forceinline__ float2 upk2(u64 v) {
    float2 f; asm("mov.b64 {%0,%1},%2;" : "=f"(f.x), "=f"(f.y) : "l"(v)); return f;
}
__device__ __forceinline__ u64 fma2(u64 a, u64 b, u64 c) {
    u64 d; asm("fma.rn.f32x2 %0,%1,%2,%3;" : "=l"(d) : "l"(a), "l"(b), "l"(c)); return d;
}
__device__ __forceinline__ u64 add2(u64 a, u64 b) {
    u64 d; asm("add.rn.f32x2 %0,%1,%2;" : "=l"(d) : "l"(a), "l"(b)); return d;
}
__device__ __forceinline__ u64 mul2(u64 a, u64 b) {
    u64 d; asm("mul.rn.f32x2 %0,%1,%2;" : "=l"(d) : "l"(a), "l"(b)); return d;
}

__device__ __forceinline__ uint32_t s2u(const void* p) {
    uint32_t a;
    asm("{ .reg .u64 t; cvta.to.shared.u64 t, %1; cvt.u32.u64 %0, t; }"
        : "=r"(a) : "l"(p));
    return a;
}
__device__ __forceinline__ uint32_t mapa_rank(uint32_t laddr, uint32_t rank) {
    uint32_t r;
    asm("mapa.shared::cluster.u32 %0, %1, %2;" : "=r"(r) : "r"(laddr), "r"(rank));
    return r;
}
__device__ __forceinline__ void mbar_init(uint32_t mb, uint32_t cnt) {
    asm volatile("mbarrier.init.shared.b64 [%0], %1;" :: "r"(mb), "r"(cnt) : "memory");
}
__device__ __forceinline__ void mbar_arrive_expect_tx(uint32_t mb, uint32_t bytes) {
    asm volatile("mbarrier.arrive.expect_tx.shared.b64 _, [%0], %1;"
                 :: "r"(mb), "r"(bytes) : "memory");
}
__device__ __forceinline__ void mbar_wait_parity(uint32_t mb, uint32_t parity) {
    asm volatile(
        "{\n\t"
        ".reg .pred P;\n\t"
        "WLOOP_%=:\n\t"
        "mbarrier.try_wait.parity.acquire.cta.shared::cta.b64 P, [%0], %1, 0x989680;\n\t"
        "@P bra.uni WDONE_%=;\n\t"
        "bra.uni WLOOP_%=;\n\t"
        "WDONE_%=:\n\t"
        "}"
        :: "r"(mb), "r"(parity) : "memory");
}
__device__ __forceinline__ void bulk_dsmem(uint32_t dst, uint32_t src,
                                           uint32_t bytes, uint32_t rembar) {
    asm volatile(
        "cp.async.bulk.shared::cluster.shared::cta.mbarrier::complete_tx::bytes "
        "[%0], [%1], %2, [%3];"
        :: "r"(dst), "r"(src), "r"(bytes), "r"(rembar) : "memory");
}
__device__ __forceinline__ void fence_proxy_async_cta() {
    asm volatile("fence.proxy.async.shared::cta;" ::: "memory");
}
__device__ __forceinline__ void cluster_sync_asm() {
    asm volatile("barrier.cluster.arrive.aligned;" ::: "memory");
    asm volatile("barrier.cluster.wait.aligned;" ::: "memory");
}
__device__ __forceinline__ u64 shflx2(u64 v, int m) {
    float2 f = upk2(v);
    f.x = __shfl_xor_sync(0xFFFFFFFFu, f.x, m);
    f.y = __shfl_xor_sync(0xFFFFFFFFu, f.y, m);
    return pk2(f.x, f.y);
}
// Fast branch-free tanh (rel err ~1e-6, fine vs 1e-3 tolerance)
__device__ __forceinline__ float ftanh(float x) {
    float ax = fabsf(x);
    float e = __expf(-2.0f * ax);
    float r = __fdividef(1.0f - e, 1.0f + e);
    return copysignf(r, x);
}

// ---------------------------------------------------------------------------
// Kernel 1: xproj[m, h] = sum_i X[m, i] * Wih[h, i] + bih[h] + bhh[h]
//   fp32 SGEMM 128x128x16, 8x8 micro-tile, inner loop in fma.rn.f32x2
// ---------------------------------------------------------------------------
__global__ void __launch_bounds__(256) xproj_kernel(
    const float* __restrict__ X,     // [32768, 512]
    const float* __restrict__ Wih,   // [512, 512]
    const float* __restrict__ bih,
    const float* __restrict__ bhh)
{
    const int BM = 128, BN = 128, BK = 16;
    __shared__ __align__(16) float As[BK][BM + 4];
    __shared__ __align__(16) float Bs[BK][BN + 4];

    const int tid = threadIdx.x;
    const int m0 = blockIdx.y * BM;
    const int n0 = blockIdx.x * BN;
    const int tx = tid & 15;
    const int ty = tid >> 4;

    u64 acc2[8][4];
#pragma unroll
    for (int i = 0; i < 8; ++i)
#pragma unroll
        for (int j = 0; j < 4; ++j) acc2[i][j] = 0ull;

    for (int k0 = 0; k0 < Idim; k0 += BK) {
#pragma unroll
        for (int q = 0; q < 2; ++q) {
            int lin = tid + 256 * q;
            int m = lin >> 2;
            int kv = (lin & 3) << 2;
            float4 va = *(const float4*)(X + (size_t)(m0 + m) * Idim + k0 + kv);
            As[kv + 0][m] = va.x; As[kv + 1][m] = va.y;
            As[kv + 2][m] = va.z; As[kv + 3][m] = va.w;
            float4 vb = *(const float4*)(Wih + (size_t)(n0 + m) * Idim + k0 + kv);
            Bs[kv + 0][m] = vb.x; Bs[kv + 1][m] = vb.y;
            Bs[kv + 2][m] = vb.z; Bs[kv + 3][m] = vb.w;
        }
        __syncthreads();

#pragma unroll
        for (int kk = 0; kk < BK; ++kk) {
            float ra[8];
            *(float4*)&ra[0] = *(const float4*)&As[kk][ty * 8];
            *(float4*)&ra[4] = *(const float4*)&As[kk][ty * 8 + 4];
            ulonglong2 rbA = *(const ulonglong2*)&Bs[kk][tx * 8];
            ulonglong2 rbB = *(const ulonglong2*)&Bs[kk][tx * 8 + 4];
            u64 rb2[4] = { rbA.x, rbA.y, rbB.x, rbB.y };
#pragma unroll
            for (int i = 0; i < 8; ++i) {
                u64 rap = pk2(ra[i], ra[i]);
#pragma unroll
                for (int j = 0; j < 4; ++j)
                    acc2[i][j] = fma2(rap, rb2[j], acc2[i][j]);
            }
        }
        __syncthreads();
    }

    u64 bs2[4];
#pragma unroll
    for (int j = 0; j < 4; ++j) {
        float blo = bih[n0 + tx * 8 + 2 * j] + bhh[n0 + tx * 8 + 2 * j];
        float bhi = bih[n0 + tx * 8 + 2 * j + 1] + bhh[n0 + tx * 8 + 2 * j + 1];
        bs2[j] = pk2(blo, bhi);
    }

#pragma unroll
    for (int i = 0; i < 8; ++i) {
        float2 p0 = upk2(add2(acc2[i][0], bs2[0]));
        float2 p1 = upk2(add2(acc2[i][1], bs2[1]));
        float2 p2 = upk2(add2(acc2[i][2], bs2[2]));
        float2 p3 = upk2(add2(acc2[i][3], bs2[3]));
        float* crow = g_xproj + (size_t)(m0 + ty * 8 + i) * Hdim + n0 + tx * 8;
        *(float4*)(crow)     = make_float4(p0.x, p0.y, p1.x, p1.y);
        *(float4*)(crow + 4) = make_float4(p2.x, p2.y, p3.x, p3.y);
    }
}

// ---------------------------------------------------------------------------
// Kernel 2: the recurrence (cluster=8, 2 batches + 64 rows per CTA).
//   Exchange redesign: history laid out source-rank-blocked
//   hist[slot][srcrank][batch][64]; each step every CTA writes its 512B slice
//   into its OWN smem, then ONE thread issues 7x cp.async.bulk (DSMEM) with
//   mbarrier::complete_tx to each peer's tx-barrier. Double-buffered barriers
//   (count=1) re-armed with arrive.expect_tx(3584). No per-lane remote stores,
//   no arrive.release (global STGs never fenced), 7 barrier updates/step.
// ---------------------------------------------------------------------------
__global__ void __launch_bounds__(256, 1) __cluster_dims__(8, 1, 1)
rnn_kernel(const float* __restrict__ Whh,   // [512, 512]
           const float* __restrict__ kern,  // [4]
           float* __restrict__ out_states,  // [B, T, H]
           float* __restrict__ out_last)    // [B, H]
{
    __shared__ __align__(16) float hist[2][8][2][64];  // 8KB  [slot][src][b][64]
    __shared__ __align__(16) float xs[2][2][8][64];    // 8KB  [buf][b][t&7][64]
    __shared__ __align__(16) float xout[2][8][64];     // 4KB  [b][t&7][64]
    __shared__ __align__(8)  u64 mbars[2];

    const int tid   = threadIdx.x;
    const int slice = blockIdx.x;          // cluster rank 0..7
    const int grp   = blockIdx.y;          // 0..15
    const int b0    = grp * 2;
    const int jlp   = tid >> 3;            // 0..31 (row pair)
    const int split = tid & 7;             // K-split 0..7
    const int jg0   = slice * 64 + jlp * 2;
    const int jg1   = jg0 + 1;

    // Register weights: for m=0..15, k_m = 4*split + 32*m, pairs (k,k+1),(k+2,k+3)
    u64 wA[32], wB[32];
#pragma unroll
    for (int m = 0; m < 16; ++m) {
        ulonglong2 ua = *(const ulonglong2*)(Whh + (size_t)jg0 * Hdim + 4 * split + 32 * m);
        ulonglong2 ub = *(const ulonglong2*)(Whh + (size_t)jg1 * Hdim + 4 * split + 32 * m);
        wA[2 * m] = ua.x; wA[2 * m + 1] = ua.y;
        wB[2 * m] = ub.x; wB[2 * m + 1] = ub.y;
    }
    const u64 kk0 = pk2(kern[0], kern[0]), kk1 = pk2(kern[1], kern[1]);
    const u64 kk2 = pk2(kern[2], kern[2]), kk3 = pk2(kern[3], kern[3]);

    // Zero both history slots (h_{-1} = 0); init + arm barriers
    for (int i = tid; i < 2 * 8 * 2 * 64; i += 256)
        ((float*)hist)[i] = 0.f;
    const uint32_t mb0 = s2u(&mbars[0]);
    if (tid == 0) {
        mbar_init(mb0, 1);
        mbar_init(mb0 + 8, 1);
        mbar_arrive_expect_tx(mb0, 7 * 512);       // step 0 data
        mbar_arrive_expect_tx(mb0 + 8, 7 * 512);   // step 1 data
    }

    // mapa bases for the 7 peers (used by tid 0 only; fully unrolled)
    const uint32_t hsrc0 = s2u(&hist[0][slice][0][0]);  // own slice, slot 0
    uint32_t dstq[8], barq[8];
#pragma unroll
    for (int q = 0; q < 8; ++q) {
        dstq[q] = mapa_rank(hsrc0, q);
        barq[q] = mapa_rank(mb0, q);
    }

    cluster_sync_asm();   // zeros + armed barriers visible cluster-wide

    // xproj staging (group = 8 steps): thread loads one float4
    const int pb  = tid >> 7;
    const int pt  = (tid >> 4) & 7;
    const int pu  = tid & 15;
    const float* xsrc = g_xproj + (size_t)(b0 + pb) * Tlen * Hdim
                        + (size_t)pt * Hdim + slice * 64 + pu * 4;
    *(float4*)&xs[0][pb][pt][pu * 4] = *(const float4*)(xsrc);        // group 0
    float4 xpre = *(const float4*)(xsrc + 8 * Hdim);                  // group 1
    __syncthreads();

    // Value role: v = split&3 -> (rsel = row, bsel = batch)
    const int v    = split & 3;
    const int bsel = v & 1;
    const int rsel = v >> 1;

    // Register M-ring (packed (b0,b1) per row)
    u64 rA0 = 0ull, rA1 = 0ull, rA2 = 0ull;
    u64 rB0 = 0ull, rB1 = 0ull, rB2 = 0ull;

    const char* histc = (const char*)hist;

    for (int t = 0; t < Tlen; ++t) {
        if (t > 0) {
            const uint32_t bsel_bar = mb0 + ((t - 1) & 1) * 8;
            mbar_wait_parity(bsel_bar, ((t - 1) >> 1) & 1);
            if (tid == 0)
                mbar_arrive_expect_tx(bsel_bar, 7 * 512);   // re-arm for t+1's data
        }

        // Stage next xproj group into the idle buffer (read 8 steps later)
        if ((t & 7) == 0) {
            int g = t >> 3;
            *(float4*)&xs[(g + 1) & 1][pb][pt][pu * 4] = xpre;
            if (t + 16 < Tlen)
                xpre = *(const float4*)(xsrc + (size_t)(t + 16) * Hdim);
        }

        // GEMV on h_{t-1}: hist[(t-1)&1][r][b][..], r = m>>1 for this thread
        const char* hb = histc + ((t - 1) & 1) * 4096 + split * 16;
        u64 aA0 = 0ull, aA0b = 0ull, aA1 = 0ull, aA1b = 0ull;
        u64 aB0 = 0ull, aB0b = 0ull, aB1 = 0ull, aB1b = 0ull;
#pragma unroll
        for (int m = 0; m < 16; ++m) {
            const char* p = hb + (m >> 1) * 512 + (m & 1) * 128;
            ulonglong2 h0 = *(const ulonglong2*)(p);         // batch 0
            ulonglong2 h1 = *(const ulonglong2*)(p + 256);   // batch 1
            aA0  = fma2(wA[2 * m],     h0.x, aA0);
            aA0b = fma2(wA[2 * m + 1], h0.y, aA0b);
            aA1  = fma2(wA[2 * m],     h1.x, aA1);
            aA1b = fma2(wA[2 * m + 1], h1.y, aA1b);
            aB0  = fma2(wB[2 * m],     h0.x, aB0);
            aB0b = fma2(wB[2 * m + 1], h0.y, aB0b);
            aB1  = fma2(wB[2 * m],     h1.x, aB1);
            aB1b = fma2(wB[2 * m + 1], h1.y, aB1b);
        }
        float2 hA0 = upk2(add2(aA0, aA0b));
        float2 hA1 = upk2(add2(aA1, aA1b));
        float2 hB0 = upk2(add2(aB0, aB0b));
        float2 hB1 = upk2(add2(aB1, aB1b));
        u64 P0 = pk2(hA0.x + hA0.y, hA1.x + hA1.y);   // row A, packed (b0,b1)
        u64 P1 = pk2(hB0.x + hB0.y, hB1.x + hB1.y);   // row B

        // Butterfly over the 8 split lanes
        P0 = add2(P0, shflx2(P0, 1)); P1 = add2(P1, shflx2(P1, 1));
        P0 = add2(P0, shflx2(P0, 2)); P1 = add2(P1, shflx2(P1, 2));
        P0 = add2(P0, shflx2(P0, 4)); P1 = add2(P1, shflx2(P1, 4));

        // 4-tap Lagrange on the register M-ring
        u64 rrA = fma2(kk0, P0, fma2(kk1, rA0, fma2(kk2, rA1, mul2(kk3, rA2))));
        u64 rrB = fma2(kk0, P1, fma2(kk1, rB0, fma2(kk2, rB1, mul2(kk3, rB2))));
        rA2 = rA1; rA1 = rA0; rA0 = P0;
        rB2 = rB1; rB1 = rB0; rB0 = P1;

        // This lane's value + activation
        float2 fA = upk2(rrA), fB = upk2(rrB);
        float pre = (v == 0) ? fA.x : (v == 1) ? fA.y : (v == 2) ? fB.x : fB.y;
        float xv  = xs[(t >> 3) & 1][bsel][t & 7][jlp * 2 + rsel];
        float val = ftanh(pre + xv);

        // Buffer output locally (flushed every 8 steps)
        if (split < 4)
            xout[bsel][t & 7][jlp * 2 + rsel] = val;

        // Assemble row pair (A,B) for this batch and store into OWN slice
        float partner = __shfl_xor_sync(0xFFFFFFFFu, val, 2);
        if (split < 2) {   // rsel==0 lanes; split == bsel here
            float2 pr = make_float2(val, partner);
            *(float2*)&hist[t & 1][slice][split][jlp * 2] = pr;
        }

        __syncthreads();   // slice complete + xout visible

        // Broadcast own 512B slice to the 7 peers via bulk DSMEM copies
        if (t < Tlen - 1 && tid == 0) {
            fence_proxy_async_cta();
            const uint32_t soff = (uint32_t)((t & 1) * 4096);
            const uint32_t src  = hsrc0 + soff;
            const uint32_t boff = (uint32_t)((t & 1) * 8);
#pragma unroll
            for (int q = 0; q < 8; ++q)
                if (q != slice)
                    bulk_dsmem(dstq[q] + soff, src, 512, barq[q] + boff);
        }

        // Flush buffered outputs (off the critical path; nothing fences them)
        if ((t & 7) == 7) {
            int t0 = t - 7;
            *(float4*)(out_states + (size_t)(b0 + pb) * Tlen * Hdim
                       + (size_t)(t0 + pt) * Hdim + slice * 64 + pu * 4)
                = *(const float4*)&xout[pb][pt][pu * 4];
        }

        if (t == Tlen - 1 && split >= 4)
            out_last[(size_t)(b0 + bsel) * Hdim + jg0 + rsel] = val;
    }

    // No CTA may exit while peers' bulk copies could still target it
    cluster_sync_asm();
}

// ---------------------------------------------------------------------------
extern "C" void kernel_launch(void* const* d_in, const int* in_sizes, int n_in,
                              void* d_out, int out_size)
{
    (void)in_sizes; (void)n_in; (void)out_size;
    const float* x    = (const float*)d_in[0];   // [32, 1024, 512]
    const float* Wih  = (const float*)d_in[1];   // [512, 512]
    const float* Whh  = (const float*)d_in[2];   // [512, 512]
    const float* bih  = (const float*)d_in[3];   // [512]
    const float* bhh  = (const float*)d_in[4];   // [512]
    const float* kern = (const float*)d_in[5];   // [4]

    float* out        = (float*)d_out;
    float* out_states = out;                                   // [32,1024,512]
    float* out_last   = out + (size_t)Bsz * Tlen * Hdim;       // [32,512]

    dim3 gg(Hdim / 128, (Bsz * Tlen) / 128);   // (4, 256)
    xproj_kernel<<<gg, 256>>>(x, Wih, bih, bhh);

    dim3 gr(8, 16);
    rnn_kernel<<<gr, 256>>>(Whh, kern, out_states, out_last);
}

// round 6
// speedup vs baseline: 1.9835x; 1.2637x over previous
#include <cuda_runtime.h>
#include <cstdint>

// Problem constants
#define Bsz 32
#define Tlen 1024
#define Idim 512
#define Hdim 512

// Scratch for the input projection (device global: no allocation allowed)
__device__ float g_xproj[(size_t)Bsz * Tlen * Hdim];  // 64 MB

// ---------------------------------------------------------------------------
// packed f32x2 helpers (FFMA2 — ptxas never auto-fuses; PTX-only)
// ---------------------------------------------------------------------------
using u64 = unsigned long long;
__device__ __forceinline__ u64 pk2(float lo, float hi) {
    u64 r; asm("mov.b64 %0,{%1,%2};" : "=l"(r) : "f"(lo), "f"(hi)); return r;
}
__device__ __forceinline__ float2 upk2(u64 v) {
    float2 f; asm("mov.b64 {%0,%1},%2;" : "=f"(f.x), "=f"(f.y) : "l"(v)); return f;
}
__device__ __forceinline__ u64 fma2(u64 a, u64 b, u64 c) {
    u64 d; asm("fma.rn.f32x2 %0,%1,%2,%3;" : "=l"(d) : "l"(a), "l"(b), "l"(c)); return d;
}
__device__ __forceinline__ u64 add2(u64 a, u64 b) {
    u64 d; asm("add.rn.f32x2 %0,%1,%2;" : "=l"(d) : "l"(a), "l"(b)); return d;
}
__device__ __forceinline__ u64 mul2(u64 a, u64 b) {
    u64 d; asm("mul.rn.f32x2 %0,%1,%2;" : "=l"(d) : "l"(a), "l"(b)); return d;
}

__device__ __forceinline__ uint32_t s2u(const void* p) {
    uint32_t a;
    asm("{ .reg .u64 t; cvta.to.shared.u64 t, %1; cvt.u32.u64 %0, t; }"
        : "=r"(a) : "l"(p));
    return a;
}
__device__ __forceinline__ uint32_t mapa_rank(uint32_t laddr, uint32_t rank) {
    uint32_t r;
    asm("mapa.shared::cluster.u32 %0, %1, %2;" : "=r"(r) : "r"(laddr), "r"(rank));
    return r;
}
__device__ __forceinline__ void mbar_init(uint32_t mb, uint32_t cnt) {
    asm volatile("mbarrier.init.shared.b64 [%0], %1;" :: "r"(mb), "r"(cnt) : "memory");
}
__device__ __forceinline__ void mbar_arrive_expect_tx(uint32_t mb, uint32_t bytes) {
    asm volatile("mbarrier.arrive.expect_tx.shared.b64 _, [%0], %1;"
                 :: "r"(mb), "r"(bytes) : "memory");
}
__device__ __forceinline__ void mbar_wait_parity(uint32_t mb, uint32_t parity) {
    asm volatile(
        "{\n\t"
        ".reg .pred P;\n\t"
        "WLOOP_%=:\n\t"
        "mbarrier.try_wait.parity.acquire.cta.shared::cta.b64 P, [%0], %1, 0x989680;\n\t"
        "@P bra.uni WDONE_%=;\n\t"
        "bra.uni WLOOP_%=;\n\t"
        "WDONE_%=:\n\t"
        "}"
        :: "r"(mb), "r"(parity) : "memory");
}
__device__ __forceinline__ void bulk_dsmem(uint32_t dst, uint32_t src,
                                           uint32_t bytes, uint32_t rembar) {
    asm volatile(
        "cp.async.bulk.shared::cluster.shared::cta.mbarrier::complete_tx::bytes "
        "[%0], [%1], %2, [%3];"
        :: "r"(dst), "r"(src), "r"(bytes), "r"(rembar) : "memory");
}
__device__ __forceinline__ void fence_proxy_async_cta() {
    asm volatile("fence.proxy.async.shared::cta;" ::: "memory");
}
__device__ __forceinline__ void cluster_sync_asm() {
    asm volatile("barrier.cluster.arrive.aligned;" ::: "memory");
    asm volatile("barrier.cluster.wait.aligned;" ::: "memory");
}
__device__ __forceinline__ u64 shflx2(u64 v, int m) {
    float2 f = upk2(v);
    f.x = __shfl_xor_sync(0xFFFFFFFFu, f.x, m);
    f.y = __shfl_xor_sync(0xFFFFFFFFu, f.y, m);
    return pk2(f.x, f.y);
}
// Fast branch-free tanh (rel err ~1e-6, fine vs 1e-3 tolerance)
__device__ __forceinline__ float ftanh(float x) {
    float ax = fabsf(x);
    float e = __expf(-2.0f * ax);
    float r = __fdividef(1.0f - e, 1.0f + e);
    return copysignf(r, x);
}

// ---------------------------------------------------------------------------
// Kernel 1: xproj[m, h] = sum_i X[m, i] * Wih[h, i] + bih[h] + bhh[h]
//   fp32 SGEMM 128x128x16, 8x8 micro-tile, inner loop in fma.rn.f32x2
// ---------------------------------------------------------------------------
__global__ void __launch_bounds__(256) xproj_kernel(
    const float* __restrict__ X,     // [32768, 512]
    const float* __restrict__ Wih,   // [512, 512]
    const float* __restrict__ bih,
    const float* __restrict__ bhh)
{
    const int BM = 128, BN = 128, BK = 16;
    __shared__ __align__(16) float As[BK][BM + 4];
    __shared__ __align__(16) float Bs[BK][BN + 4];

    const int tid = threadIdx.x;
    const int m0 = blockIdx.y * BM;
    const int n0 = blockIdx.x * BN;
    const int tx = tid & 15;
    const int ty = tid >> 4;

    u64 acc2[8][4];
#pragma unroll
    for (int i = 0; i < 8; ++i)
#pragma unroll
        for (int j = 0; j < 4; ++j) acc2[i][j] = 0ull;

    for (int k0 = 0; k0 < Idim; k0 += BK) {
#pragma unroll
        for (int q = 0; q < 2; ++q) {
            int lin = tid + 256 * q;
            int m = lin >> 2;
            int kv = (lin & 3) << 2;
            float4 va = *(const float4*)(X + (size_t)(m0 + m) * Idim + k0 + kv);
            As[kv + 0][m] = va.x; As[kv + 1][m] = va.y;
            As[kv + 2][m] = va.z; As[kv + 3][m] = va.w;
            float4 vb = *(const float4*)(Wih + (size_t)(n0 + m) * Idim + k0 + kv);
            Bs[kv + 0][m] = vb.x; Bs[kv + 1][m] = vb.y;
            Bs[kv + 2][m] = vb.z; Bs[kv + 3][m] = vb.w;
        }
        __syncthreads();

#pragma unroll
        for (int kk = 0; kk < BK; ++kk) {
            float ra[8];
            *(float4*)&ra[0] = *(const float4*)&As[kk][ty * 8];
            *(float4*)&ra[4] = *(const float4*)&As[kk][ty * 8 + 4];
            ulonglong2 rbA = *(const ulonglong2*)&Bs[kk][tx * 8];
            ulonglong2 rbB = *(const ulonglong2*)&Bs[kk][tx * 8 + 4];
            u64 rb2[4] = { rbA.x, rbA.y, rbB.x, rbB.y };
#pragma unroll
            for (int i = 0; i < 8; ++i) {
                u64 rap = pk2(ra[i], ra[i]);
#pragma unroll
                for (int j = 0; j < 4; ++j)
                    acc2[i][j] = fma2(rap, rb2[j], acc2[i][j]);
            }
        }
        __syncthreads();
    }

    u64 bs2[4];
#pragma unroll
    for (int j = 0; j < 4; ++j) {
        float blo = bih[n0 + tx * 8 + 2 * j] + bhh[n0 + tx * 8 + 2 * j];
        float bhi = bih[n0 + tx * 8 + 2 * j + 1] + bhh[n0 + tx * 8 + 2 * j + 1];
        bs2[j] = pk2(blo, bhi);
    }

#pragma unroll
    for (int i = 0; i < 8; ++i) {
        float2 p0 = upk2(add2(acc2[i][0], bs2[0]));
        float2 p1 = upk2(add2(acc2[i][1], bs2[1]));
        float2 p2 = upk2(add2(acc2[i][2], bs2[2]));
        float2 p3 = upk2(add2(acc2[i][3], bs2[3]));
        float* crow = g_xproj + (size_t)(m0 + ty * 8 + i) * Hdim + n0 + tx * 8;
        *(float4*)(crow)     = make_float4(p0.x, p0.y, p1.x, p1.y);
        *(float4*)(crow + 4) = make_float4(p2.x, p2.y, p3.x, p3.y);
    }
}

// ---------------------------------------------------------------------------
// Kernel 2: the recurrence — ALL-TO-ALL OF M-PARTIALS.
//   CTA q owns Whh COLUMNS [64q,64q+64) (in registers) and h rows [64q,64q+64).
//   Step t:  A) sum 8 arriving partials -> M_{t-1}[own rows], Lagrange taps on
//   a register M-ring, tanh -> h_t[own rows] (local!).  B) each WARP w computes
//   the 64-row partial chunk Whh[64w:64w+64, cols]·h_t for peer w and fires its
//   own 512B cp.async.bulk as soon as the chunk is done (comm overlaps compute;
//   h never crosses CTAs).  Pair-swizzled layout keeps both the partial store
//   and the 8-source gather conflict-free. Double-buffered tx-barriers.
// ---------------------------------------------------------------------------
__global__ void __launch_bounds__(256, 1) __cluster_dims__(8, 1, 1)
rnn_kernel(const float* __restrict__ Whh,   // [512, 512]
           const float* __restrict__ kern,  // [4]
           float* __restrict__ out_states,  // [B, T, H]
           float* __restrict__ out_last)    // [B, H]
{
    __shared__ __align__(16) float arr[2][8][128];   // 8KB [slot][src][swz 512B]
    __shared__ __align__(16) float stg[2][8][128];   // 8KB [slot][warp][512B]
    __shared__ __align__(16) float hloc[2][64];      // h_t[own rows], batch-major
    __shared__ __align__(16) float xs[2][2][8][64];  // 8KB xproj stage
    __shared__ __align__(16) float xout[2][8][64];   // 4KB output stage
    __shared__ __align__(8)  u64 mbars[2];

    const int tid   = threadIdx.x;
    const int lane  = tid & 31;
    const int w     = tid >> 5;            // warp id == destination peer
    const int slice = blockIdx.x;          // cluster rank 0..7
    const int grp   = blockIdx.y;          // 0..15
    const int b0    = grp * 2;

    // Register weights: rows 64w+2*lane, +1 of Whh, columns [64*slice, +64),
    // packed along K (pairs of adjacent columns).
    u64 wR0[32], wR1[32];
    {
        const float* r0p = Whh + (size_t)(64 * w + 2 * lane) * Hdim + 64 * slice;
        const float* r1p = r0p + Hdim;
#pragma unroll
        for (int m = 0; m < 16; ++m) {
            ulonglong2 u0 = *(const ulonglong2*)(r0p + 4 * m);
            ulonglong2 u1 = *(const ulonglong2*)(r1p + 4 * m);
            wR0[2 * m] = u0.x; wR0[2 * m + 1] = u0.y;
            wR1[2 * m] = u1.x; wR1[2 * m + 1] = u1.y;
        }
    }
    const u64 kk0 = pk2(kern[0], kern[0]), kk1 = pk2(kern[1], kern[1]);
    const u64 kk2 = pk2(kern[2], kern[2]), kk3 = pk2(kern[3], kern[3]);

    // Init + arm tx-barriers (count 1, expect 7*512 B per slot)
    const uint32_t mb0 = s2u(&mbars[0]);
    if (tid == 0) {
        mbar_init(mb0, 1);
        mbar_init(mb0 + 8, 1);
        mbar_arrive_expect_tx(mb0, 7 * 512);
        mbar_arrive_expect_tx(mb0 + 8, 7 * 512);
    }

    // Per-warp remote targets (peer w): its arr slot at src index = MY slice
    const uint32_t arr_b = s2u(arr);
    const uint32_t dst_b = mapa_rank(arr_b, w) + (uint32_t)(slice * 512);
    const uint32_t bar_b = mapa_rank(mb0, w);

    cluster_sync_asm();   // barrier init visible cluster-wide

    // xproj staging: one float4 per thread per 8-step group
    const int pb  = tid >> 7;
    const int pt  = (tid >> 4) & 7;
    const int pu  = tid & 15;
    const float* xsrc = g_xproj + (size_t)(b0 + pb) * Tlen * Hdim
                        + (size_t)pt * Hdim + slice * 64 + pu * 4;
    *(float4*)&xs[0][pb][pt][pu * 4] = *(const float4*)(xsrc);        // group 0
    float4 xpre = *(const float4*)(xsrc + 8 * Hdim);                  // group 1
    __syncthreads();

    // Sum-phase roles: thread -> (row, quad); quad handles source pair 2q,2q+1
    const int row  = tid >> 2;     // 0..63 (own-row index)
    const int quad = tid & 3;

    // Register M-ring: M_{t-2}, M_{t-3}, M_{t-4} for this row, packed (b0,b1)
    u64 ring0 = 0ull, ring1 = 0ull, ring2 = 0ull;

    const char* arrc = (const char*)arr;

    for (int t = 0; t < Tlen; ++t) {
        // ---- Phase A: gather M_{t-1}, taps, tanh -> h_t (own rows) ----
        u64 Mt1 = 0ull;
        if (t > 0) {
            const uint32_t bar = mb0 + ((t - 1) & 1) * 8;
            mbar_wait_parity(bar, ((t - 1) >> 1) & 1);
            if (tid == 0)
                mbar_arrive_expect_tx(bar, 7 * 512);   // re-arm for step t+2

            const char* ab = arrc + ((t - 1) & 1) * 4096;
            const int s0 = 2 * quad, s1 = 2 * quad + 1;
            const int pbk = row >> 1, rb = (row & 1) * 8;
            u64 v0 = *(const u64*)(ab + s0 * 512 + (((pbk + 5 * s0) & 31) * 16 + rb));
            u64 v1 = *(const u64*)(ab + s1 * 512 + (((pbk + 5 * s1) & 31) * 16 + rb));
            u64 m = add2(v0, v1);
            m = add2(m, shflx2(m, 1));
            m = add2(m, shflx2(m, 2));
            Mt1 = m;                       // all 4 quad lanes hold full M[row]
        }

        // Stage next xproj group into the idle buffer (read 8 steps later)
        if ((t & 7) == 0) {
            int g = t >> 3;
            *(float4*)&xs[(g + 1) & 1][pb][pt][pu * 4] = xpre;
            if (t + 16 < Tlen)
                xpre = *(const float4*)(xsrc + (size_t)(t + 16) * Hdim);
        }

        // 4-tap Lagrange on the register M-ring
        u64 rr = fma2(kk0, Mt1, fma2(kk1, ring0, fma2(kk2, ring1, mul2(kk3, ring2))));
        ring2 = ring1; ring1 = ring0; ring0 = Mt1;

        if (quad < 2) {                    // quad == batch
            float2 rf = upk2(rr);
            float pre = (quad == 0) ? rf.x : rf.y;
            float val = ftanh(pre + xs[(t >> 3) & 1][quad][t & 7][row]);
            hloc[quad][row] = val;
            xout[quad][t & 7][row] = val;
            if (t == Tlen - 1)
                out_last[(size_t)(b0 + quad) * Hdim + slice * 64 + row] = val;
        }

        __syncthreads();   // hloc/xout ready; xs stage ordered

        // ---- Phase B: per-warp partial chunk GEMV + immediate send ----
        if (t < Tlen - 1) {
            u64 aA0 = 0ull, cA0 = 0ull, aA1 = 0ull, cA1 = 0ull;
            u64 aB0 = 0ull, cB0 = 0ull, aB1 = 0ull, cB1 = 0ull;
#pragma unroll
            for (int m = 0; m < 16; ++m) {
                ulonglong2 h0 = *(const ulonglong2*)&hloc[0][4 * m];
                ulonglong2 h1 = *(const ulonglong2*)&hloc[1][4 * m];
                aA0 = fma2(wR0[2 * m],     h0.x, aA0);
                cA0 = fma2(wR0[2 * m + 1], h0.y, cA0);
                aA1 = fma2(wR0[2 * m],     h1.x, aA1);
                cA1 = fma2(wR0[2 * m + 1], h1.y, cA1);
                aB0 = fma2(wR1[2 * m],     h0.x, aB0);
                cB0 = fma2(wR1[2 * m + 1], h0.y, cB0);
                aB1 = fma2(wR1[2 * m],     h1.x, aB1);
                cB1 = fma2(wR1[2 * m + 1], h1.y, cB1);
            }
            float2 fA0 = upk2(add2(aA0, cA0));
            float2 fA1 = upk2(add2(aA1, cA1));
            float2 fB0 = upk2(add2(aB0, cB0));
            float2 fB1 = upk2(add2(aB1, cB1));
            // rows 2*lane, 2*lane+1 of chunk w; values (r0b0,r0b1,r1b0,r1b1)
            float4 o = make_float4(fA0.x + fA0.y, fA1.x + fA1.y,
                                   fB0.x + fB0.y, fB1.x + fB1.y);
            float* dstp = (w == slice) ? &arr[t & 1][slice][0]
                                       : &stg[t & 1][w][0];
            *(float4*)(dstp + ((lane + 5 * slice) & 31) * 4) = o;
            __syncwarp();
            if (w != slice && lane == 0) {
                fence_proxy_async_cta();
                bulk_dsmem(dst_b + (uint32_t)((t & 1) * 4096),
                           s2u(&stg[t & 1][w][0]), 512,
                           bar_b + (uint32_t)((t & 1) * 8));
            }
        }

        // Flush buffered outputs (off the critical path)
        if ((t & 7) == 7) {
            int t0 = t - 7;
            *(float4*)(out_states + (size_t)(b0 + pb) * Tlen * Hdim
                       + (size_t)(t0 + pt) * Hdim + slice * 64 + pu * 4)
                = *(const float4*)&xout[pb][pt][pu * 4];
        }

        __syncthreads();   // own-chunk STS visible to next step's gather
    }

    // No CTA may exit while peers' bulk copies could still target it
    cluster_sync_asm();
}

// ---------------------------------------------------------------------------
extern "C" void kernel_launch(void* const* d_in, const int* in_sizes, int n_in,
                              void* d_out, int out_size)
{
    (void)in_sizes; (void)n_in; (void)out_size;
    const float* x    = (const float*)d_in[0];   // [32, 1024, 512]
    const float* Wih  = (const float*)d_in[1];   // [512, 512]
    const float* Whh  = (const float*)d_in[2];   // [512, 512]
    const float* bih  = (const float*)d_in[3];   // [512]
    const float* bhh  = (const float*)d_in[4];   // [512]
    const float* kern = (const float*)d_in[5];   // [4]

    float* out        = (float*)d_out;
    float* out_states = out;                                   // [32,1024,512]
    float* out_last   = out + (size_t)Bsz * Tlen * Hdim;       // [32,512]

    dim3 gg(Hdim / 128, (Bsz * Tlen) / 128);   // (4, 256)
    xproj_kernel<<<gg, 256>>>(x, Wih, bih, bhh);

    dim3 gr(8, 16);
    rnn_kernel<<<gr, 256>>>(Whh, kern, out_states, out_last);
}